// round 7
// baseline (speedup 1.0000x reference)
#include <cuda_runtime.h>
#include <cuda_bf16.h>
#include <cstdint>

// Problem constants: x (16, 64, 56, 56) fp32, K=7, PAD=3, STRIDE=1, DIL=1
// out (16, 64, 49, 3136) fp32 ; out[n,c,kk,l] = center[l] - patch_kk[l]
#define NC_TOTAL   1024      // 16*64 planes
#define H_IMG      56
#define W_IMG      56
#define L_IMG      (H_IMG * W_IMG)        // 3136
#define KWIN       7
#define KK         (KWIN * KWIN)          // 49
#define TILE_H     62                     // 3 + 56 + 3
#define TILE_W     64                     // 4 + 56 + 3 (+1 spare), keeps rows 16B-aligned
#define TILE_ELEMS (TILE_H * TILE_W)      // 3968 floats = 15872 B
#define THREADS    256
#define NCHUNK     (L_IMG / 4)            // 784 float4 chunks per plane
#define NMAIN      3                      // 784 = 256*3 + 16 tail
#define NBLOCKS    (NC_TOTAL * KWIN)      // 7168: one block per (plane, i-row)

__global__ __launch_bounds__(THREADS, 4)
void subtraction_kernel(const float* __restrict__ x, float* __restrict__ out) {
    __shared__ float tile[TILE_ELEMS];

    const int bi  = blockIdx.x;
    const int nc  = bi / KWIN;           // plane index
    const int i   = bi - nc * KWIN;      // kernel row handled by this block
    const int tid = threadIdx.x;

    // -------- Stage the (n,c) plane into smem with zero padding --------
    const float* __restrict__ src = x + (size_t)nc * L_IMG;
    #pragma unroll 4
    for (int idx = tid; idx < TILE_ELEMS; idx += THREADS) {
        const int r  = idx >> 6;       // / 64
        const int cc = idx & 63;       // % 64
        const int h  = r - 3;
        const int w  = cc - 4;
        float v = 0.0f;
        if ((unsigned)h < H_IMG && (unsigned)w < W_IMG)
            v = src[h * W_IMG + w];
        tile[idx] = v;
    }
    __syncthreads();

    // This block writes only kk = i*7 .. i*7+6.
    float* __restrict__ outbase = out + (size_t)nc * (KK * L_IMG)
                                      + (size_t)(i * KWIN) * L_IMG;

    // -------- Load phase: hoist center + patch rows for all 3 chunks --------
    // Per chunk: center = 1 aligned LDS.128, patch row i = 3 aligned LDS.128.
    // j-shifts are compile-time register selects from e[][1..10].
    float  e[NMAIN][12];
    float4 c4[NMAIN];
    int    lbase[NMAIN];
    #pragma unroll
    for (int k = 0; k < NMAIN; k++) {
        const int chunk = tid + k * THREADS;
        const int l = chunk << 2;            // multiple of 4; stays inside one row
        const int h = l / W_IMG;
        const int w = l - h * W_IMG;         // multiple of 4
        lbase[k] = l;
        c4[k] = *reinterpret_cast<const float4*>(&tile[(h + 3) * TILE_W + (w + 4)]);
        const float* prow = &tile[(h + i) * TILE_W + w];
        *reinterpret_cast<float4*>(&e[k][0]) = *reinterpret_cast<const float4*>(prow);
        *reinterpret_cast<float4*>(&e[k][4]) = *reinterpret_cast<const float4*>(prow + 4);
        *reinterpret_cast<float4*>(&e[k][8]) = *reinterpret_cast<const float4*>(prow + 8);
    }

    // -------- Store phase: sweep one j-stream at a time (CTA writes ONE
    // contiguous 12.5 KB stream at a time instead of 7 interleaved) --------
    #pragma unroll
    for (int j = 0; j < KWIN; j++) {
        #pragma unroll
        for (int k = 0; k < NMAIN; k++) {
            float4 o;
            o.x = c4[k].x - e[k][j + 1];
            o.y = c4[k].y - e[k][j + 2];
            o.z = c4[k].z - e[k][j + 3];
            o.w = c4[k].w - e[k][j + 4];
            __stcs(reinterpret_cast<float4*>(&outbase[j * L_IMG + lbase[k]]), o);
        }
    }

    // -------- Tail: chunks 768..783 (16 threads) --------
    if (tid < (NCHUNK - NMAIN * THREADS)) {
        const int l = (NMAIN * THREADS + tid) << 2;
        const int h = l / W_IMG;
        const int w = l - h * W_IMG;
        const float4 c = *reinterpret_cast<const float4*>(&tile[(h + 3) * TILE_W + (w + 4)]);
        const float* prow = &tile[(h + i) * TILE_W + w];
        float et[12];
        *reinterpret_cast<float4*>(&et[0]) = *reinterpret_cast<const float4*>(prow);
        *reinterpret_cast<float4*>(&et[4]) = *reinterpret_cast<const float4*>(prow + 4);
        *reinterpret_cast<float4*>(&et[8]) = *reinterpret_cast<const float4*>(prow + 8);
        #pragma unroll
        for (int j = 0; j < KWIN; j++) {
            float4 o;
            o.x = c.x - et[j + 1];
            o.y = c.y - et[j + 2];
            o.z = c.z - et[j + 3];
            o.w = c.w - et[j + 4];
            __stcs(reinterpret_cast<float4*>(&outbase[j * L_IMG + l]), o);
        }
    }
}

extern "C" void kernel_launch(void* const* d_in, const int* in_sizes, int n_in,
                              void* d_out, int out_size) {
    const float* x = (const float*)d_in[0];
    float* out     = (float*)d_out;
    subtraction_kernel<<<NBLOCKS, THREADS>>>(x, out);
}